// round 7
// baseline (speedup 1.0000x reference)
#include <cuda_runtime.h>
#include <cuda_fp16.h>
#include <math.h>
#include <float.h>

#define BATCH  8
#define NPT    1024
#define TOT    8388608        // BATCH*NPT*NPT
#define BLOCK  512
#define NWB    16             // warps per block
#define MAXG   152
#define MAXBLK 19
#define PARTN  (BATCH*MAXBLK*NPT)

// -------- persistent device state (reset each launch) ---------------------
__device__ __align__(16) __half g_Kh[TOT];        // K fp16 [b][i][j]
__device__ __align__(16) float  g_part[2][PARTN]; // double-buffered partials
__device__ int g_maxM[BATCH];
__device__ int g_bad;
__device__ int g_maxdiff[10];
__device__ unsigned g_batCnt[BATCH];
__device__ unsigned g_blkCnt;
__device__ unsigned g_hvyCount;                   // monotonic across launches
__device__ volatile unsigned g_hvyGen;

__device__ __forceinline__ void heavy_barrier(int nb) {
    __threadfence();
    __syncthreads();
    if (threadIdx.x == 0) {
        unsigned g = g_hvyGen;
        unsigned t = atomicAdd(&g_hvyCount, 1u);
        if (t % (unsigned)nb == (unsigned)(nb - 1)) {
            __threadfence();
            g_hvyGen = g + 1u;
        } else {
            while (g_hvyGen == g) {}
        }
    }
    __syncthreads();
}

__device__ __forceinline__ void rel_inc(unsigned* p) {
    asm volatile("red.release.gpu.global.add.u32 [%0], %1;"
                 :: "l"(p), "r"(1u) : "memory");
}
__device__ __forceinline__ unsigned acq_ld(const unsigned* p) {
    unsigned v;
    asm volatile("ld.acquire.gpu.global.u32 %0, [%1];"
                 : "=r"(v) : "l"(p) : "memory");
    return v;
}
__device__ __forceinline__ int ld_cg_i(const int* p) {
    int v;
    asm volatile("ld.global.cg.b32 %0, [%1];" : "=r"(v) : "l"(p) : "memory");
    return v;
}
__device__ __forceinline__ float2 h2f(unsigned q) {
    __half2 h = *reinterpret_cast<__half2*>(&q);
    return __half22float2(h);
}

__global__ void __launch_bounds__(BLOCK, 1)
sot_kernel(const float* __restrict__ coord1, const float* __restrict__ prob1,
           const float* __restrict__ coord2, const float* __restrict__ prob2,
           float* __restrict__ Pout)
{
    const int tid  = threadIdx.x;
    const int bid  = blockIdx.x;
    const int nb   = gridDim.x;
    const int lane = tid & 31;
    const int wid  = tid >> 5;

    const int myb  = (bid * BATCH) / nb;
    const int blk0 = (myb * nb + BATCH - 1) / BATCH;
    const int blk1 = ((myb + 1) * nb + BATCH - 1) / BATCH;
    const int nbb  = blk1 - blk0;
    const int lidx = bid - blk0;
    const int r_lo = (lidx * NPT) / nbb;
    const int r_hi = ((lidx + 1) * NPT) / nbb;
    const int nr   = r_hi - r_lo;

    __shared__ __align__(16) float s_v[2][NPT];
    __shared__ float s_u[2][64];
    __shared__ __align__(16) float s_b[NPT];
    __shared__ float s_a[64];
    __shared__ float2 s_xi[64];
    __shared__ float s_red[NWB];
    __shared__ float s_suma, s_sumb;
    __shared__ int   s_bad, s_f0, s_f1;

    __half* Kbh = g_Kh + ((size_t)myb << 20);

    // ---------------- resets ----------------------------------------------
    if (tid == 0) s_bad = 0;
    if (bid == 0) {
        if (tid == 1)               g_blkCnt = 0;
        if (tid == 2)               g_bad = 0;
        if (tid >= 8  && tid < 16)  g_batCnt[tid - 8] = 0;
        if (tid >= 16 && tid < 26)  g_maxdiff[tid - 16] = 0;
        if (tid >= 32 && tid < 40)  g_maxM[tid - 32] = 0;
    }

    // ---------------- block-local prob sums, a, b, coords -----------------
    const float*  p1b  = prob1 + (myb << 10);
    const float2* p2b2 = (const float2*)(prob2 + (myb << 10));
    {
        const float2* p1b2 = (const float2*)p1b;
        float2 x1 = p1b2[tid];
        float2 x2 = p2b2[tid];
        float sa = (x1.x + 1e-8f) + (x1.y + 1e-8f);
        float sb = (x2.x + 1e-8f) + (x2.y + 1e-8f);
#pragma unroll
        for (int o = 16; o; o >>= 1) {
            sa += __shfl_xor_sync(0xffffffffu, sa, o);
            sb += __shfl_xor_sync(0xffffffffu, sb, o);
        }
        if (lane == 0) s_red[wid] = sa;
        __syncthreads();
        if (wid == 0) {
            float t = (lane < NWB) ? s_red[lane] : 0.f;
#pragma unroll
            for (int o = 16; o; o >>= 1) t += __shfl_xor_sync(0xffffffffu, t, o);
            if (lane == 0) s_suma = t;
        }
        __syncthreads();
        if (lane == 0) s_red[wid] = sb;
        __syncthreads();
        if (wid == 0) {
            float t = (lane < NWB) ? s_red[lane] : 0.f;
#pragma unroll
            for (int o = 16; o; o >>= 1) t += __shfl_xor_sync(0xffffffffu, t, o);
            if (lane == 0) s_sumb = t;
        }
        __syncthreads();
    }
    {
        float2 x2 = p2b2[tid];
        ((float2*)s_b)[tid] = make_float2((x2.x + 1e-8f) / s_sumb,
                                          (x2.y + 1e-8f) / s_sumb);
        if (tid < nr) {
            s_a[tid]  = (p1b[r_lo + tid] + 1e-8f) / s_suma;
            s_xi[tid] = ((const float2*)(coord1 + (myb << 11)))[r_lo + tid];
        }
        ((float2*)s_v[1])[tid] = make_float2(1.0f/1024.0f, 1.0f/1024.0f);
        if (tid < 64) s_u[1][tid] = 1.0f/1024.0f;
    }
    heavy_barrier(nb);

    // ---------------- light barriers ---------------------------------------
    unsigned phB = 0, phG = 0;
    auto batch_bar = [&]() {
        phB++;
        __syncthreads();
        if (tid == 0) {
            rel_inc(&g_batCnt[myb]);
            while (acq_ld(&g_batCnt[myb]) < phB * (unsigned)nbb) {}
        }
        __syncthreads();
    };
    auto global_bar = [&]() {
        phG++;
        __syncthreads();
        if (tid == 0) {
            if (s_bad) { atomicOr(&g_bad, 1); s_bad = 0; }
            rel_inc(&g_blkCnt);
            while (acq_ld(&g_blkCnt) < phG * (unsigned)nb) {}
        }
        __syncthreads();
    };

    // ---------------- maxM over own rows ----------------------------------
    {
        const float2* cy = (const float2*)(coord2 + (myb << 11));
        float m = 0.f;
        for (int r = wid; r < nr; r += NWB) {
            float2 xi = s_xi[r];
            for (int j = lane; j < NPT; j += 32) {
                float2 yy = cy[j];
                float d0 = xi.x - yy.x, d1 = xi.y - yy.y;
                m = fmaxf(m, d0 * d0 + d1 * d1);
            }
        }
#pragma unroll
        for (int o = 16; o; o >>= 1) m = fmaxf(m, __shfl_xor_sync(0xffffffffu, m, o));
        if (lane == 0) s_red[wid] = m;
        __syncthreads();
        if (wid == 0) {
            float t = (lane < NWB) ? s_red[lane] : 0.f;
#pragma unroll
            for (int o = 16; o; o >>= 1) t = fmaxf(t, __shfl_xor_sync(0xffffffffu, t, o));
            if (lane == 0 && tid == 0) atomicMax(&g_maxM[myb], __float_as_int(t));
        }
    }
    batch_bar();

    // ---------------- K materialization (fp16, 4 cols/thread) ---------------
    {
        float nscale = -10.0f / __int_as_float(ld_cg_i(&g_maxM[myb]));
        const int cg = tid & 255;         // columns 4cg..4cg+3
        const int h  = tid >> 8;          // row half
        const int h_lo = (h * nr) >> 1, h_hi = ((h + 1) * nr) >> 1;
        const float4* cy4 = (const float4*)(coord2 + (myb << 11));
        float4 y0 = cy4[cg * 2];          // points 4cg, 4cg+1
        float4 y1 = cy4[cg * 2 + 1];      // points 4cg+2, 4cg+3
        uint2* Krow = (uint2*)(Kbh + ((size_t)r_lo << 10)) + cg;
        for (int r = h_lo; r < h_hi; ++r) {
            float2 xi = s_xi[r];
            float a0 = xi.x - y0.x, b0 = xi.y - y0.y;
            float a1 = xi.x - y0.z, b1 = xi.y - y0.w;
            float a2 = xi.x - y1.x, b2 = xi.y - y1.y;
            float a3 = xi.x - y1.z, b3 = xi.y - y1.w;
            float e0 = __expf((a0 * a0 + b0 * b0) * nscale);
            float e1 = __expf((a1 * a1 + b1 * b1) * nscale);
            float e2 = __expf((a2 * a2 + b2 * b2) * nscale);
            float e3 = __expf((a3 * a3 + b3 * b3) * nscale);
            __half2 hA = __floats2half2_rn(e0, e1);
            __half2 hB = __floats2half2_rn(e2, e3);
            uint2 w;
            w.x = *reinterpret_cast<unsigned*>(&hA);
            w.y = *reinterpret_cast<unsigned*>(&hB);
            Krow[(size_t)r << 8] = w;
        }
    }
    __syncthreads();   // K visible block-wide (writers == readers' block)

    // ---------------- A-pass: column partials from u -----------------------
    // warp = 8 column-groups (8 cols via uint4) x 4 row-quarters (lane>>3)
    auto do_A = [&](int cp, int par) {
        const uint4* K4 = (const uint4*)(Kbh + ((size_t)r_lo << 10));
        const int g = (wid << 3) + (lane & 7);
        const int q = lane >> 3;
        const int q_lo = (q * nr) >> 2, q_hi = ((q + 1) * nr) >> 2;
        float acc0 = 0.f, acc1 = 0.f, acc2 = 0.f, acc3 = 0.f;
        float acc4 = 0.f, acc5 = 0.f, acc6 = 0.f, acc7 = 0.f;
        for (int r = q_lo; r < q_hi; ++r) {
            float u = s_u[cp][r];
            uint4 m = __ldg(K4 + (r << 7) + g);
            float2 f0 = h2f(m.x), f1 = h2f(m.y), f2 = h2f(m.z), f3 = h2f(m.w);
            acc0 = fmaf(f0.x, u, acc0); acc1 = fmaf(f0.y, u, acc1);
            acc2 = fmaf(f1.x, u, acc2); acc3 = fmaf(f1.y, u, acc3);
            acc4 = fmaf(f2.x, u, acc4); acc5 = fmaf(f2.y, u, acc5);
            acc6 = fmaf(f3.x, u, acc6); acc7 = fmaf(f3.y, u, acc7);
        }
#pragma unroll
        for (int o = 8; o <= 16; o <<= 1) {
            acc0 += __shfl_xor_sync(0xffffffffu, acc0, o);
            acc1 += __shfl_xor_sync(0xffffffffu, acc1, o);
            acc2 += __shfl_xor_sync(0xffffffffu, acc2, o);
            acc3 += __shfl_xor_sync(0xffffffffu, acc3, o);
            acc4 += __shfl_xor_sync(0xffffffffu, acc4, o);
            acc5 += __shfl_xor_sync(0xffffffffu, acc5, o);
            acc6 += __shfl_xor_sync(0xffffffffu, acc6, o);
            acc7 += __shfl_xor_sync(0xffffffffu, acc7, o);
        }
        if (q == 0) {
            float4* pd = (float4*)(g_part[par] + ((myb * MAXBLK + lidx) << 10));
            pd[g * 2]     = make_float4(acc0, acc1, acc2, acc3);
            pd[g * 2 + 1] = make_float4(acc4, acc5, acc6, acc7);
        }
    };
    do_A(1, 0);         // initial partials: u0 = 1/1024 (preloaded in s_u[1])

    // ---------------- final output -----------------------------------------
    auto write_final = [&](int buf) {
        const float4* v4 = (const float4*)s_v[buf];
        for (int r = wid; r < nr; r += NWB) {
            float u = s_u[buf][r];
            const uint4* k4 = (const uint4*)(Kbh + ((size_t)(r_lo + r) << 10));
            float4* o4 = (float4*)(Pout + ((size_t)myb << 20) + ((size_t)(r_lo + r) << 10));
#pragma unroll
            for (int s = 0; s < 4; ++s) {
                int ix = (s * 32 + lane);
                uint4 m = __ldg(k4 + ix);
                float2 f0 = h2f(m.x), f1 = h2f(m.y), f2 = h2f(m.z), f3 = h2f(m.w);
                float4 va = v4[ix * 2], vb = v4[ix * 2 + 1];
                float4 pA, pB;
                pA.x = (u * f0.x) * va.x;  pA.y = (u * f0.y) * va.y;
                pA.z = (u * f1.x) * va.z;  pA.w = (u * f1.y) * va.w;
                pB.x = (u * f2.x) * vb.x;  pB.y = (u * f2.y) * vb.y;
                pB.z = (u * f3.x) * vb.z;  pB.w = (u * f3.y) * vb.w;
                __stcs(o4 + ix * 2, pA);
                __stcs(o4 + ix * 2 + 1, pB);
            }
        }
    };

    // ---------------- Sinkhorn chunks --------------------------------------
    int parity = 0;
    for (int c = 0; c < 10; ++c) {
        const int cp = c & 1;
        for (int it = 0; it < 10; ++it) {
            batch_bar();
            // ---- B: v = b / sum_of_partials ------------------------------
            {
                const float2* pb = (const float2*)(g_part[parity] + ((myb * MAXBLK) << 10));
                float2 kt = make_float2(0.f, 0.f);
                if (nbb == 19) {
#pragma unroll
                    for (int p = 0; p < 19; ++p) {
                        float2 x = __ldcg(pb + (p << 9) + tid);
                        kt.x += x.x; kt.y += x.y;
                    }
                } else {
                    for (int p = 0; p < nbb; ++p) {
                        float2 x = __ldcg(pb + (p << 9) + tid);
                        kt.x += x.x; kt.y += x.y;
                    }
                }
                float2 bb = ((const float2*)s_b)[tid];
                float vx = bb.x / kt.x;
                float vy = bb.y / kt.y;
                if (kt.x == 0.f || kt.y == 0.f ||
                    !(fabsf(vx) <= FLT_MAX) || !(fabsf(vy) <= FLT_MAX))
                    s_bad = 1;
                ((float2*)s_v[cp])[tid] = make_float2(vx, vy);
            }
            __syncthreads();
            // ---- u-pass: u_i = a_i / dot(K_row_i, v) ---------------------
            {
                const float4* v4 = (const float4*)s_v[cp];
                float4 vr[8];
#pragma unroll
                for (int s = 0; s < 4; ++s) {
                    int ix = (s * 32 + lane) * 2;
                    vr[2 * s]     = v4[ix];
                    vr[2 * s + 1] = v4[ix + 1];
                }
                for (int r = wid; r < nr; r += NWB) {
                    const uint4* m4 = (const uint4*)(Kbh + ((size_t)(r_lo + r) << 10));
                    float d0 = 0.f, d1 = 0.f, d2 = 0.f, d3 = 0.f;
#pragma unroll
                    for (int s = 0; s < 4; ++s) {
                        uint4 m = __ldg(m4 + s * 32 + lane);
                        float2 f0 = h2f(m.x), f1 = h2f(m.y);
                        float2 f2 = h2f(m.z), f3 = h2f(m.w);
                        float4 va = vr[2 * s], vb = vr[2 * s + 1];
                        d0 = fmaf(f0.x, va.x, fmaf(f0.y, va.y, d0));
                        d1 = fmaf(f1.x, va.z, fmaf(f1.y, va.w, d1));
                        d2 = fmaf(f2.x, vb.x, fmaf(f2.y, vb.y, d2));
                        d3 = fmaf(f3.x, vb.z, fmaf(f3.y, vb.w, d3));
                    }
                    float dot = (d0 + d1) + (d2 + d3);
#pragma unroll
                    for (int o = 16; o; o >>= 1) dot += __shfl_xor_sync(0xffffffffu, dot, o);
                    if (lane == 0) {
                        float uu = s_a[r] / dot;
                        if (dot == 0.f || !(fabsf(uu) <= FLT_MAX)) s_bad = 1;
                        s_u[cp][r] = uu;
                    }
                }
            }
            __syncthreads();
            do_A(cp, parity ^ 1);
            parity ^= 1;
        }

        // ---- chunk check: maxdiff without materializing P -----------------
        {
            const float4* v4c = (const float4*)s_v[cp];
            const float4* v4p = (const float4*)s_v[cp ^ 1];
            float lm = 0.f;
            for (int r = wid; r < nr; r += NWB) {
                float u  = s_u[cp][r];
                float up = s_u[cp ^ 1][r];
                const uint4* k4 = (const uint4*)(Kbh + ((size_t)(r_lo + r) << 10));
#pragma unroll
                for (int s = 0; s < 4; ++s) {
                    int ix = (s * 32 + lane);
                    uint4 m = __ldg(k4 + ix);
                    float2 f0 = h2f(m.x), f1 = h2f(m.y);
                    float2 f2 = h2f(m.z), f3 = h2f(m.w);
                    float4 va = v4c[ix * 2], vb = v4c[ix * 2 + 1];
                    float4 pa = v4p[ix * 2], pb = v4p[ix * 2 + 1];
                    float x0 = fabsf((u * f0.x) * va.x - (up * f0.x) * pa.x);
                    float x1 = fabsf((u * f0.y) * va.y - (up * f0.y) * pa.y);
                    float x2 = fabsf((u * f1.x) * va.z - (up * f1.x) * pa.z);
                    float x3 = fabsf((u * f1.y) * va.w - (up * f1.y) * pa.w);
                    float x4 = fabsf((u * f2.x) * vb.x - (up * f2.x) * pb.x);
                    float x5 = fabsf((u * f2.y) * vb.y - (up * f2.y) * pb.y);
                    float x6 = fabsf((u * f3.x) * vb.z - (up * f3.x) * pb.z);
                    float x7 = fabsf((u * f3.y) * vb.w - (up * f3.y) * pb.w);
                    lm = fmaxf(lm, fmaxf(fmaxf(fmaxf(x0, x1), fmaxf(x2, x3)),
                                         fmaxf(fmaxf(x4, x5), fmaxf(x6, x7))));
                }
            }
#pragma unroll
            for (int o = 16; o; o >>= 1) lm = fmaxf(lm, __shfl_xor_sync(0xffffffffu, lm, o));
            if (lane == 0) s_red[wid] = lm;
            __syncthreads();
            if (wid == 0) {
                float t = (lane < NWB) ? s_red[lane] : 0.f;
#pragma unroll
                for (int o = 16; o; o >>= 1) t = fmaxf(t, __shfl_xor_sync(0xffffffffu, t, o));
                if (lane == 0 && tid == 0) atomicMax(&g_maxdiff[c], __float_as_int(t));
            }
        }
        global_bar();                      // tid0's release orders its atomics
        if (tid == 0) {
            s_f0 = ld_cg_i(&g_bad);
            s_f1 = ld_cg_i(&g_maxdiff[c]);
        }
        __syncthreads();
        if (s_f0) {                        // bad: previous chunk's P (or P0)
            write_final(cp ^ 1);
            return;
        }
        if (__int_as_float(s_f1) < 1e-3f || c == 9) {
            write_final(cp);
            return;
        }
    }
}

extern "C" void kernel_launch(void* const* d_in, const int* in_sizes, int n_in,
                              void* d_out, int out_size) {
    static int nsm = 0;
    if (nsm == 0) {
        int dev = 0; cudaGetDevice(&dev);
        int v = 0;
        if (cudaDeviceGetAttribute(&v, cudaDevAttrMultiProcessorCount, dev)
                != cudaSuccess || v <= 0) v = 148;
        if (v > MAXG) v = MAXG;
        if (v < BATCH) v = BATCH;
        nsm = v;
    }
    const float* c1 = nullptr; const float* p1 = nullptr;
    const float* c2 = nullptr; const float* p2 = nullptr;
    for (int i = 0; i < n_in; ++i) {
        if (in_sizes[i] == BATCH * NPT * 2) {
            if (!c1) c1 = (const float*)d_in[i]; else c2 = (const float*)d_in[i];
        } else if (in_sizes[i] == BATCH * NPT) {
            if (!p1) p1 = (const float*)d_in[i]; else p2 = (const float*)d_in[i];
        }
    }
    sot_kernel<<<nsm, BLOCK>>>(c1, p1, c2, p2, (float*)d_out);
}

// round 8
// speedup vs baseline: 1.2302x; 1.2302x over previous
#include <cuda_runtime.h>
#include <cuda_fp16.h>
#include <math.h>
#include <float.h>

#define BATCH  8
#define NPT    1024
#define TOT    8388608        // BATCH*NPT*NPT
#define BLOCK  512
#define NWB    16             // warps per block
#define MAXG   152
#define MAXBLK 19
#define PARTN  (BATCH*MAXBLK*NPT)
#define DYNSM  65536          // 16 warps x 1024 floats staging buffer

// -------- persistent device state (reset each launch) ---------------------
__device__ __align__(16) __half g_Kh[TOT];        // K fp16 [b][i][j]
__device__ __align__(16) float  g_part[2][PARTN]; // double-buffered partials
__device__ int g_maxM[BATCH];
__device__ int g_bad;
__device__ int g_maxdiff[10];
__device__ unsigned g_batCnt[BATCH];
__device__ unsigned g_blkCnt;
__device__ unsigned g_hvyCount;                   // monotonic across launches
__device__ volatile unsigned g_hvyGen;

__device__ __forceinline__ void heavy_barrier(int nb) {
    __threadfence();
    __syncthreads();
    if (threadIdx.x == 0) {
        unsigned g = g_hvyGen;
        unsigned t = atomicAdd(&g_hvyCount, 1u);
        if (t % (unsigned)nb == (unsigned)(nb - 1)) {
            __threadfence();
            g_hvyGen = g + 1u;
        } else {
            while (g_hvyGen == g) {}
        }
    }
    __syncthreads();
}

__device__ __forceinline__ void rel_inc(unsigned* p) {
    asm volatile("red.release.gpu.global.add.u32 [%0], %1;"
                 :: "l"(p), "r"(1u) : "memory");
}
__device__ __forceinline__ unsigned acq_ld(const unsigned* p) {
    unsigned v;
    asm volatile("ld.acquire.gpu.global.u32 %0, [%1];"
                 : "=r"(v) : "l"(p) : "memory");
    return v;
}
__device__ __forceinline__ int ld_cg_i(const int* p) {
    int v;
    asm volatile("ld.global.cg.b32 %0, [%1];" : "=r"(v) : "l"(p) : "memory");
    return v;
}
__device__ __forceinline__ float2 h2f(unsigned q) {
    __half2 h = *reinterpret_cast<__half2*>(&q);
    return __half22float2(h);
}

__global__ void __launch_bounds__(BLOCK, 1)
sot_kernel(const float* __restrict__ coord1, const float* __restrict__ prob1,
           const float* __restrict__ coord2, const float* __restrict__ prob2,
           float* __restrict__ Pout)
{
    extern __shared__ __align__(16) float s_dyn[];   // [16][1024] staging

    const int tid  = threadIdx.x;
    const int bid  = blockIdx.x;
    const int nb   = gridDim.x;
    const int lane = tid & 31;
    const int wid  = tid >> 5;

    const int myb  = (bid * BATCH) / nb;
    const int blk0 = (myb * nb + BATCH - 1) / BATCH;
    const int blk1 = ((myb + 1) * nb + BATCH - 1) / BATCH;
    const int nbb  = blk1 - blk0;
    const int lidx = bid - blk0;
    const int r_lo = (lidx * NPT) / nbb;
    const int r_hi = ((lidx + 1) * NPT) / nbb;
    const int nr   = r_hi - r_lo;

    __shared__ __align__(16) float s_v[2][NPT];
    __shared__ float s_u[2][64];
    __shared__ __align__(16) float s_b[NPT];
    __shared__ float s_a[64];
    __shared__ float2 s_xi[64];
    __shared__ float s_red[NWB];
    __shared__ float s_suma, s_sumb;
    __shared__ int   s_bad, s_f0, s_f1;

    __half* Kbh = g_Kh + ((size_t)myb << 20);

    // ---------------- resets ----------------------------------------------
    if (tid == 0) s_bad = 0;
    if (bid == 0) {
        if (tid == 1)               g_blkCnt = 0;
        if (tid == 2)               g_bad = 0;
        if (tid >= 8  && tid < 16)  g_batCnt[tid - 8] = 0;
        if (tid >= 16 && tid < 26)  g_maxdiff[tid - 16] = 0;
        if (tid >= 32 && tid < 40)  g_maxM[tid - 32] = 0;
    }

    // ---------------- block-local prob sums, a, b, coords -----------------
    const float*  p1b  = prob1 + (myb << 10);
    const float2* p2b2 = (const float2*)(prob2 + (myb << 10));
    {
        const float2* p1b2 = (const float2*)p1b;
        float2 x1 = p1b2[tid];
        float2 x2 = p2b2[tid];
        float sa = (x1.x + 1e-8f) + (x1.y + 1e-8f);
        float sb = (x2.x + 1e-8f) + (x2.y + 1e-8f);
#pragma unroll
        for (int o = 16; o; o >>= 1) {
            sa += __shfl_xor_sync(0xffffffffu, sa, o);
            sb += __shfl_xor_sync(0xffffffffu, sb, o);
        }
        if (lane == 0) s_red[wid] = sa;
        __syncthreads();
        if (wid == 0) {
            float t = (lane < NWB) ? s_red[lane] : 0.f;
#pragma unroll
            for (int o = 16; o; o >>= 1) t += __shfl_xor_sync(0xffffffffu, t, o);
            if (lane == 0) s_suma = t;
        }
        __syncthreads();
        if (lane == 0) s_red[wid] = sb;
        __syncthreads();
        if (wid == 0) {
            float t = (lane < NWB) ? s_red[lane] : 0.f;
#pragma unroll
            for (int o = 16; o; o >>= 1) t += __shfl_xor_sync(0xffffffffu, t, o);
            if (lane == 0) s_sumb = t;
        }
        __syncthreads();
    }
    {
        float2 x2 = p2b2[tid];
        ((float2*)s_b)[tid] = make_float2((x2.x + 1e-8f) / s_sumb,
                                          (x2.y + 1e-8f) / s_sumb);
        if (tid < nr) {
            s_a[tid]  = (p1b[r_lo + tid] + 1e-8f) / s_suma;
            s_xi[tid] = ((const float2*)(coord1 + (myb << 11)))[r_lo + tid];
        }
        ((float2*)s_v[1])[tid] = make_float2(1.0f/1024.0f, 1.0f/1024.0f);
        if (tid < 64) s_u[1][tid] = 1.0f/1024.0f;
    }
    heavy_barrier(nb);

    // ---------------- light barriers ---------------------------------------
    unsigned phB = 0, phG = 0;
    auto batch_bar = [&]() {
        phB++;
        __syncthreads();
        if (tid == 0) {
            rel_inc(&g_batCnt[myb]);
            while (acq_ld(&g_batCnt[myb]) < phB * (unsigned)nbb) {}
        }
        __syncthreads();
    };
    auto global_bar = [&]() {
        phG++;
        __syncthreads();
        if (tid == 0) {
            if (s_bad) { atomicOr(&g_bad, 1); s_bad = 0; }
            rel_inc(&g_blkCnt);
            while (acq_ld(&g_blkCnt) < phG * (unsigned)nb) {}
        }
        __syncthreads();
    };

    // ---------------- maxM over own rows ----------------------------------
    {
        const float2* cy = (const float2*)(coord2 + (myb << 11));
        float m = 0.f;
        for (int r = wid; r < nr; r += NWB) {
            float2 xi = s_xi[r];
            for (int j = lane; j < NPT; j += 32) {
                float2 yy = cy[j];
                float d0 = xi.x - yy.x, d1 = xi.y - yy.y;
                m = fmaxf(m, d0 * d0 + d1 * d1);
            }
        }
#pragma unroll
        for (int o = 16; o; o >>= 1) m = fmaxf(m, __shfl_xor_sync(0xffffffffu, m, o));
        if (lane == 0) s_red[wid] = m;
        __syncthreads();
        if (wid == 0) {
            float t = (lane < NWB) ? s_red[lane] : 0.f;
#pragma unroll
            for (int o = 16; o; o >>= 1) t = fmaxf(t, __shfl_xor_sync(0xffffffffu, t, o));
            if (lane == 0 && tid == 0) atomicMax(&g_maxM[myb], __float_as_int(t));
        }
    }
    batch_bar();

    // ---------------- K materialization (fp16) + initial partials ----------
    {
        float nscale = -10.0f / __int_as_float(ld_cg_i(&g_maxM[myb]));
        const float4* cy4 = (const float4*)(coord2 + (myb << 11));
        float4 yy = cy4[tid];                 // cols 2tid, 2tid+1
        float2 acc = make_float2(0.f, 0.f);
        __half2* Krow = (__half2*)(Kbh + ((size_t)r_lo << 10)) + tid;
        for (int r = 0; r < nr; ++r) {
            float2 xi = s_xi[r];
            float d0 = xi.x - yy.x, d1 = xi.y - yy.y;
            float d2 = xi.x - yy.z, d3 = xi.y - yy.w;
            float kx = __expf((d0 * d0 + d1 * d1) * nscale);
            float ky = __expf((d2 * d2 + d3 * d3) * nscale);
            __half2 h = __floats2half2_rn(kx, ky);
            Krow[(size_t)r << 9] = h;
            float2 f = __half22float2(h);     // rounded values for consistency
            acc.x += f.x; acc.y += f.y;
        }
        float2* pm0 = (float2*)(g_part[0] + ((myb * MAXBLK + lidx) << 10));
        pm0[tid] = make_float2(acc.x * (1.0f/1024.0f), acc.y * (1.0f/1024.0f));
    }

    // ---------------- final output ----------------------------------------
    auto write_final = [&](int buf) {
        const float4* v4 = (const float4*)s_v[buf];
        for (int r = wid; r < nr; r += NWB) {
            float u = s_u[buf][r];
            const uint2* k2 = (const uint2*)(Kbh + ((size_t)(r_lo + r) << 10));
            float4* o4 = (float4*)(Pout + ((size_t)myb << 20) + ((size_t)(r_lo + r) << 10));
#pragma unroll
            for (int c = 0; c < 8; ++c) {
                uint2 q = __ldg(k2 + lane + 32 * c);
                float2 f0 = h2f(q.x), f1 = h2f(q.y);
                float4 vv = v4[lane + 32 * c];
                float4 pn;
                pn.x = (u * f0.x) * vv.x;  pn.y = (u * f0.y) * vv.y;
                pn.z = (u * f1.x) * vv.z;  pn.w = (u * f1.y) * vv.w;
                __stcs(o4 + lane + 32 * c, pn);
            }
        }
    };

    // ---------------- Sinkhorn chunks --------------------------------------
    int parity = 0;
    for (int c = 0; c < 10; ++c) {
        const int cp = c & 1;
        for (int it = 0; it < 10; ++it) {
            batch_bar();
            // ---- B: v = b / sum_of_partials ------------------------------
            {
                const float2* pb = (const float2*)(g_part[parity] + ((myb * MAXBLK) << 10));
                float2 kt = make_float2(0.f, 0.f);
                if (nbb == 19) {
#pragma unroll
                    for (int p = 0; p < 19; ++p) {
                        float2 x = __ldcg(pb + (p << 9) + tid);
                        kt.x += x.x; kt.y += x.y;
                    }
                } else {
                    for (int p = 0; p < nbb; ++p) {
                        float2 x = __ldcg(pb + (p << 9) + tid);
                        kt.x += x.x; kt.y += x.y;
                    }
                }
                float2 bb = ((const float2*)s_b)[tid];
                float vx = bb.x / kt.x;
                float vy = bb.y / kt.y;
                if (kt.x == 0.f || kt.y == 0.f ||
                    !(fabsf(vx) <= FLT_MAX) || !(fabsf(vy) <= FLT_MAX))
                    s_bad = 1;
                ((float2*)s_v[cp])[tid] = make_float2(vx, vy);
            }
            __syncthreads();
            // ---- fused u-pass + column-partial accumulation --------------
            {
                const float4* v4 = (const float4*)s_v[cp];
                float racc[32];
#pragma unroll
                for (int i = 0; i < 32; ++i) racc[i] = 0.f;
                for (int r = wid; r < nr; r += NWB) {
                    const uint2* m2 = (const uint2*)(Kbh + ((size_t)(r_lo + r) << 10));
                    float kf[32];
                    float d0 = 0.f, d1 = 0.f;
#pragma unroll
                    for (int cch = 0; cch < 8; ++cch) {
                        uint2 q = __ldg(m2 + lane + 32 * cch);
                        float2 fa = h2f(q.x), fb = h2f(q.y);
                        kf[4*cch]   = fa.x;  kf[4*cch+1] = fa.y;
                        kf[4*cch+2] = fb.x;  kf[4*cch+3] = fb.y;
                        float4 vv = v4[lane + 32 * cch];
                        d0 = fmaf(fa.x, vv.x, fmaf(fa.y, vv.y, d0));
                        d1 = fmaf(fb.x, vv.z, fmaf(fb.y, vv.w, d1));
                    }
                    float dot = d0 + d1;
#pragma unroll
                    for (int o = 16; o; o >>= 1) dot += __shfl_xor_sync(0xffffffffu, dot, o);
                    float uu = s_a[r] / dot;       // uniform across warp
                    if (lane == 0) {
                        if (dot == 0.f || !(fabsf(uu) <= FLT_MAX)) s_bad = 1;
                        s_u[cp][r] = uu;
                    }
#pragma unroll
                    for (int i = 0; i < 32; ++i)
                        racc[i] = fmaf(kf[i], uu, racc[i]);
                }
                // stage per-warp partials (cols 4*(lane+32*cch)+0..3)
                float4* buf4 = (float4*)(s_dyn + (wid << 10));
#pragma unroll
                for (int cch = 0; cch < 8; ++cch)
                    buf4[lane + 32 * cch] = make_float4(racc[4*cch], racc[4*cch+1],
                                                        racc[4*cch+2], racc[4*cch+3]);
                __syncthreads();
                // deterministic 16-way cross-warp reduction, cols 2tid,2tid+1
                float2 sum = make_float2(0.f, 0.f);
#pragma unroll
                for (int w = 0; w < NWB; ++w) {
                    float2 x = ((const float2*)(s_dyn + (w << 10)))[tid];
                    sum.x += x.x; sum.y += x.y;
                }
                float2* pd = (float2*)(g_part[parity ^ 1] + ((myb * MAXBLK + lidx) << 10));
                pd[tid] = sum;
            }
            parity ^= 1;
        }

        // ---- chunk check: maxdiff without materializing P -----------------
        {
            const float4* v4c = (const float4*)s_v[cp];
            const float4* v4p = (const float4*)s_v[cp ^ 1];
            float lm = 0.f;
            for (int r = wid; r < nr; r += NWB) {
                float u  = s_u[cp][r];
                float up = s_u[cp ^ 1][r];
                const uint2* k2 = (const uint2*)(Kbh + ((size_t)(r_lo + r) << 10));
#pragma unroll
                for (int cch = 0; cch < 8; ++cch) {
                    uint2 q = __ldg(k2 + lane + 32 * cch);
                    float2 f0 = h2f(q.x), f1 = h2f(q.y);
                    float4 vv = v4c[lane + 32 * cch];
                    float4 vp = v4p[lane + 32 * cch];
                    float dx = fabsf((u * f0.x) * vv.x - (up * f0.x) * vp.x);
                    float dy = fabsf((u * f0.y) * vv.y - (up * f0.y) * vp.y);
                    float dz = fabsf((u * f1.x) * vv.z - (up * f1.x) * vp.z);
                    float dw = fabsf((u * f1.y) * vv.w - (up * f1.y) * vp.w);
                    lm = fmaxf(lm, fmaxf(fmaxf(dx, dy), fmaxf(dz, dw)));
                }
            }
#pragma unroll
            for (int o = 16; o; o >>= 1) lm = fmaxf(lm, __shfl_xor_sync(0xffffffffu, lm, o));
            if (lane == 0) s_red[wid] = lm;
            __syncthreads();
            if (wid == 0) {
                float t = (lane < NWB) ? s_red[lane] : 0.f;
#pragma unroll
                for (int o = 16; o; o >>= 1) t = fmaxf(t, __shfl_xor_sync(0xffffffffu, t, o));
                if (lane == 0 && tid == 0) atomicMax(&g_maxdiff[c], __float_as_int(t));
            }
        }
        global_bar();                      // tid0's release orders its atomics
        if (tid == 0) {
            s_f0 = ld_cg_i(&g_bad);
            s_f1 = ld_cg_i(&g_maxdiff[c]);
        }
        __syncthreads();
        if (s_f0) {                        // bad: previous chunk's P (or P0)
            write_final(cp ^ 1);
            return;
        }
        if (__int_as_float(s_f1) < 1e-3f || c == 9) {
            write_final(cp);
            return;
        }
    }
}

extern "C" void kernel_launch(void* const* d_in, const int* in_sizes, int n_in,
                              void* d_out, int out_size) {
    static int nsm = 0;
    if (nsm == 0) {
        int dev = 0; cudaGetDevice(&dev);
        int v = 0;
        if (cudaDeviceGetAttribute(&v, cudaDevAttrMultiProcessorCount, dev)
                != cudaSuccess || v <= 0) v = 148;
        if (v > MAXG) v = MAXG;
        if (v < BATCH) v = BATCH;
        nsm = v;
    }
    // opt-in to 64KB dynamic smem (idempotent host-side call, capture-safe)
    cudaFuncSetAttribute(sot_kernel, cudaFuncAttributeMaxDynamicSharedMemorySize,
                         DYNSM);
    const float* c1 = nullptr; const float* p1 = nullptr;
    const float* c2 = nullptr; const float* p2 = nullptr;
    for (int i = 0; i < n_in; ++i) {
        if (in_sizes[i] == BATCH * NPT * 2) {
            if (!c1) c1 = (const float*)d_in[i]; else c2 = (const float*)d_in[i];
        } else if (in_sizes[i] == BATCH * NPT) {
            if (!p1) p1 = (const float*)d_in[i]; else p2 = (const float*)d_in[i];
        }
    }
    sot_kernel<<<nsm, BLOCK, DYNSM>>>(c1, p1, c2, p2, (float*)d_out);
}